// round 14
// baseline (speedup 1.0000x reference)
#include <cuda_runtime.h>
#include <cuda_bf16.h>
#include <cstdint>

#define NN   10368
#define CC   512
#define HS   128
#define NT   64            // n per kA CTA
#define NSPL 162           // NN / NT

// ---------------- device scratch ----------------
__device__ __nv_bfloat16 g_Wcat[256 * CC];            // [256][512] K-major
__device__ __nv_bfloat16 g_fiT[NN * HS];              // fi^T [n][h]
__device__ __nv_bfloat16 g_Tp[NSPL * HS * CC];        // bf16 T partials [sp][h][c]
__device__ __nv_bfloat16 g_Tt[CC * HS];               // T^T [c][h]

// ---------------- helpers ----------------
__device__ __forceinline__ uint32_t smem_u32(const void* p) {
    uint32_t a;
    asm("{ .reg .u64 t; cvta.to.shared.u64 t, %1; cvt.u32.u64 %0, t; }" : "=r"(a) : "l"(p));
    return a;
}
__device__ __forceinline__ void ldsm4(uint32_t addr, uint32_t& r0, uint32_t& r1,
                                      uint32_t& r2, uint32_t& r3) {
    asm volatile("ldmatrix.sync.aligned.m8n8.x4.shared.b16 {%0,%1,%2,%3}, [%4];"
                 : "=r"(r0), "=r"(r1), "=r"(r2), "=r"(r3) : "r"(addr));
}
__device__ __forceinline__ void ldsm4t(uint32_t addr, uint32_t& r0, uint32_t& r1,
                                       uint32_t& r2, uint32_t& r3) {
    asm volatile("ldmatrix.sync.aligned.m8n8.x4.trans.shared.b16 {%0,%1,%2,%3}, [%4];"
                 : "=r"(r0), "=r"(r1), "=r"(r2), "=r"(r3) : "r"(addr));
}
__device__ __forceinline__ void mma_bf16(float* c, uint32_t a0, uint32_t a1, uint32_t a2,
                                         uint32_t a3, uint32_t b0, uint32_t b1) {
    asm volatile("mma.sync.aligned.m16n8k16.row.col.f32.bf16.bf16.f32 "
                 "{%0,%1,%2,%3}, {%4,%5,%6,%7}, {%8,%9}, {%0,%1,%2,%3};"
                 : "+f"(c[0]), "+f"(c[1]), "+f"(c[2]), "+f"(c[3])
                 : "r"(a0), "r"(a1), "r"(a2), "r"(a3), "r"(b0), "r"(b1));
}
#define CP16(dst, src)  asm volatile("cp.async.cg.shared.global [%0], [%1], 16;" :: "r"(dst), "l"(src))
#define CP_COMMIT()     asm volatile("cp.async.commit_group;" ::: "memory")
#define CP_WAIT0()      asm volatile("cp.async.wait_group 0;" ::: "memory")
#define CP_WAIT1()      asm volatile("cp.async.wait_group 1;" ::: "memory")

// ---- kA smem layout (bytes) ----
#define XB_OFF   0                     // retained x bf16 [512 c][72] : 73728
#define A_OFF    73728                 // Wcat stages x2 [256 m][72]  : 36864 each
#define A_ST     36864
#define XS_OFF   147456                // x fp32 stages x2 [64][64]   : 16384 each
#define XS_ST    16384
#define KA_SMEM  180224
#define XBS      72                    // bf16 stride
#define FIS      136                   // fi staging stride (bf16)

// ======================= kA: fused prepass + f + T-partial =======================
__global__ __launch_bounds__(256) void kA(const float* __restrict__ x,
                                          const float* __restrict__ bi,
                                          const float* __restrict__ bj) {
    extern __shared__ __align__(16) char sm[];
    const uint32_t sb = smem_u32(sm);
    const int tid = threadIdx.x, lane = tid & 31, wid = tid >> 5;
    const int n0 = blockIdx.x * NT;

    // ---- phase 1: f = Wcat @ x_chunk.  M=256, N=64, K=512 ----
    const int mBase = (wid >> 1) * 64, nB1 = (wid & 1) * 32;
    float acc[4][4][4] = {};

    auto cpA = [&](int s) {
        const uint32_t st = sb + A_OFF + (s & 1) * A_ST;
#pragma unroll
        for (int i = tid; i < 2048; i += 256) {
            const int row = i >> 3, q = (i & 7) * 8;
            CP16(st + (uint32_t)(row * XBS + q) * 2, g_Wcat + (size_t)row * CC + s * 64 + q);
        }
    };
    auto cpX = [&](int s) {
        const uint32_t st = sb + XS_OFF + (s & 1) * XS_ST;
#pragma unroll
        for (int i = tid; i < 1024; i += 256) {
            const int c = i >> 4, q = (i & 15) * 4;
            CP16(st + (uint32_t)(c * 64 + q) * 4, x + (size_t)(s * 64 + c) * NN + n0 + q);
        }
    };

    cpA(0); cpX(0); CP_COMMIT();
    for (int s = 0; s < 8; s++) {
        if (s < 7) { cpA(s + 1); cpX(s + 1); CP_COMMIT(); CP_WAIT1(); }
        else       { CP_WAIT0(); }
        __syncthreads();
        // convert fp32 stage -> retained xb rows [s*64 .. s*64+64)
        {
            const float* xs = (const float*)(sm + XS_OFF + (s & 1) * XS_ST);
            __nv_bfloat16* xb = (__nv_bfloat16*)sm;
#pragma unroll
            for (int i = tid; i < 512; i += 256) {
                const int c = i >> 3, q = (i & 7) * 8;
                float4 v0 = *(const float4*)(xs + c * 64 + q);
                float4 v1 = *(const float4*)(xs + c * 64 + q + 4);
                uint4 o;
                __nv_bfloat162 h;
                h = __floats2bfloat162_rn(v0.x, v0.y); o.x = *(uint32_t*)&h;
                h = __floats2bfloat162_rn(v0.z, v0.w); o.y = *(uint32_t*)&h;
                h = __floats2bfloat162_rn(v1.x, v1.y); o.z = *(uint32_t*)&h;
                h = __floats2bfloat162_rn(v1.z, v1.w); o.w = *(uint32_t*)&h;
                *(uint4*)(xb + (size_t)(s * 64 + c) * XBS + q) = o;
            }
        }
        __syncthreads();
        const uint32_t stA = sb + A_OFF + (s & 1) * A_ST;
#pragma unroll
        for (int kk = 0; kk < 4; kk++) {
            uint32_t af[4][4], bf[2][4];
#pragma unroll
            for (int mf = 0; mf < 4; mf++)
                ldsm4(stA + (uint32_t)((mBase + mf * 16 + (lane & 15)) * XBS
                                       + kk * 16 + (lane >> 4) * 8) * 2,
                      af[mf][0], af[mf][1], af[mf][2], af[mf][3]);
            // B via trans-ldmatrix from retained xb [c=k rows][n cols]
            // FIXED group order: m0=(k0-7,n0-7) m1=(k8-15,n0-7) m2=(k0-7,n+8) m3=(k8-15,n+8)
#pragma unroll
            for (int nt = 0; nt < 2; nt++) {
                const int crow = s * 64 + kk * 16 + (lane & 7) + (((lane >> 3) & 1) << 3);
                const int ncol = nB1 + nt * 16 + ((lane >> 4) << 3);
                ldsm4t(sb + (uint32_t)(crow * XBS + ncol) * 2,
                       bf[nt][0], bf[nt][1], bf[nt][2], bf[nt][3]);
            }
#pragma unroll
            for (int mf = 0; mf < 4; mf++)
#pragma unroll
                for (int nq = 0; nq < 2; nq++) {
                    mma_bf16(acc[mf][nq * 2],     af[mf][0], af[mf][1], af[mf][2], af[mf][3],
                             bf[nq][0], bf[nq][1]);
                    mma_bf16(acc[mf][nq * 2 + 1], af[mf][0], af[mf][1], af[mf][2], af[mf][3],
                             bf[nq][2], bf[nq][3]);
                }
        }
    }
    __syncthreads();

    // ---- phase-1 epilogue: stage fi (transposed) and fj (row-major) ----
    __nv_bfloat16* fjS = (__nv_bfloat16*)(sm + A_OFF);            // [128 h][72]
    __nv_bfloat16* fiS = (__nv_bfloat16*)(sm + A_OFF + A_ST);     // [64 n][136]
    {
        const int r = lane >> 2, cc2 = (lane & 3) * 2;
        if (wid < 4) {
#pragma unroll
            for (int mf = 0; mf < 4; mf++)
#pragma unroll
                for (int e = 0; e < 2; e++) {
                    const int m = mBase + mf * 16 + r + e * 8;
                    const float bias = bi[m];
#pragma unroll
                    for (int nf = 0; nf < 4; nf++) {
                        const int nl = nB1 + nf * 8 + cc2;
                        fiS[(nl + 0) * FIS + m] = __float2bfloat16(acc[mf][nf][e * 2] + bias);
                        fiS[(nl + 1) * FIS + m] = __float2bfloat16(acc[mf][nf][e * 2 + 1] + bias);
                    }
                }
        } else {
#pragma unroll
            for (int mf = 0; mf < 4; mf++)
#pragma unroll
                for (int e = 0; e < 2; e++) {
                    const int h = mBase - 128 + mf * 16 + r + e * 8;
                    const float bias = bj[h];
#pragma unroll
                    for (int nf = 0; nf < 4; nf++) {
                        const int nl = nB1 + nf * 8 + cc2;
                        *(__nv_bfloat162*)(fjS + h * XBS + nl) =
                            __floats2bfloat162_rn(acc[mf][nf][e * 2] + bias,
                                                  acc[mf][nf][e * 2 + 1] + bias);
                    }
                }
        }
    }
    __syncthreads();
#pragma unroll
    for (int i = tid; i < 1024; i += 256) {
        const int row = i >> 4, q = (i & 15) * 8;
        *(uint4*)(g_fiT + (size_t)(n0 + row) * HS + q) = *(uint4*)(fiS + row * FIS + q);
    }

    // ---- phase 2: Tp[sp][h][c] = sum_n fjS[h][n] * xb[c][n]  (K=64) ----
    const int mB2 = (wid >> 1) * 32, cW = (wid & 1) * 32;
    const int r = lane >> 2, cc2 = (lane & 3) * 2;
    const int b_r = ((lane >> 4) << 3) + (lane & 7), b_k = ((lane >> 3) & 1) * 8;
    __nv_bfloat16* xb = (__nv_bfloat16*)sm;
    __nv_bfloat16* tS = fiS;
    const uint32_t fjA = smem_u32(fjS);

    for (int cb = 0; cb < 8; cb++) {
        float a2[2][4][4] = {};
#pragma unroll
        for (int kk = 0; kk < 4; kk++) {
            uint32_t af[2][4], bf[2][4];
#pragma unroll
            for (int mf = 0; mf < 2; mf++)
                ldsm4(fjA + (uint32_t)((mB2 + mf * 16 + (lane & 15)) * XBS
                                       + kk * 16 + (lane >> 4) * 8) * 2,
                      af[mf][0], af[mf][1], af[mf][2], af[mf][3]);
#pragma unroll
            for (int nq = 0; nq < 2; nq++)
                ldsm4(sb + (uint32_t)((cb * 64 + cW + nq * 16 + b_r) * XBS
                                      + kk * 16 + b_k) * 2,
                      bf[nq][0], bf[nq][1], bf[nq][2], bf[nq][3]);
#pragma unroll
            for (int mf = 0; mf < 2; mf++)
#pragma unroll
                for (int nq = 0; nq < 2; nq++) {
                    mma_bf16(a2[mf][nq * 2],     af[mf][0], af[mf][1], af[mf][2], af[mf][3],
                             bf[nq][0], bf[nq][1]);
                    mma_bf16(a2[mf][nq * 2 + 1], af[mf][0], af[mf][1], af[mf][2], af[mf][3],
                             bf[nq][2], bf[nq][3]);
                }
        }
        __syncthreads();
#pragma unroll
        for (int mf = 0; mf < 2; mf++)
#pragma unroll
            for (int e = 0; e < 2; e++) {
                const int h = mB2 + mf * 16 + r + e * 8;
#pragma unroll
                for (int nf = 0; nf < 4; nf++) {
                    const int cl = cW + nf * 8 + cc2;
                    *(__nv_bfloat162*)(tS + h * XBS + cl) =
                        __floats2bfloat162_rn(a2[mf][nf][e * 2], a2[mf][nf][e * 2 + 1]);
                }
            }
        __syncthreads();
        __nv_bfloat16* dst = g_Tp + (size_t)blockIdx.x * HS * CC + cb * 64;
#pragma unroll
        for (int i = tid; i < 1024; i += 256) {
            const int row = i >> 3, q = (i & 7) * 8;
            *(uint4*)(dst + (size_t)row * CC + q) = *(uint4*)(tS + row * XBS + q);
        }
    }
}

// ======================= k0: weights -> bf16 concat =======================
__global__ void k0_w(const float* __restrict__ Wi, const float* __restrict__ Wj) {
    int i = blockIdx.x * 256 + threadIdx.x;
    if (i < 256 * CC)
        g_Wcat[i] = __float2bfloat16(i < HS * CC ? Wi[i] : Wj[i - HS * CC]);
}

// ======================= kred: Tt[c][h] = bf16(sum_sp Tp) =======================
__global__ void kred() {
    const int idx = blockIdx.x * 256 + threadIdx.x;
    const int i8 = idx * 8;
    const int h = i8 >> 9, c0 = i8 & 511;
    float s[8] = {};
    for (int p = 0; p < NSPL; p++) {
        uint4 v = *(const uint4*)(g_Tp + (size_t)p * HS * CC + h * CC + c0);
        const __nv_bfloat162* b = (const __nv_bfloat162*)&v;
#pragma unroll
        for (int j = 0; j < 4; j++) {
            float2 f = __bfloat1622float2(b[j]);
            s[2 * j] += f.x; s[2 * j + 1] += f.y;
        }
    }
#pragma unroll
    for (int j = 0; j < 8; j++)
        g_Tt[(size_t)(c0 + j) * HS + h] = __float2bfloat16(s[j]);
}

// ======================= k4: out = x + scale * (fiT @ Tt^T)^T =======================
#define SM_STRIDE 72
#define STAGE_A   (128 * SM_STRIDE * 2)
#define STAGE_B   (64 * SM_STRIDE * 2)
#define STAGE_SZ  (STAGE_A + STAGE_B)
#define SMEM_TOT  (2 * STAGE_SZ)
#define EPS 132

__device__ __forceinline__ void gemm_pipe(const __nv_bfloat16* __restrict__ Ag, size_t lda,
                                          const __nv_bfloat16* __restrict__ Bg, size_t ldb,
                                          int K, float acc[4][2][4], char* sm) {
    const int tid = threadIdx.x, lane = tid & 31, wid = tid >> 5;
    const int mBase = (wid >> 2) * 64, nBase = (wid & 3) * 16;
    const uint32_t sbase = smem_u32(sm);

    const int a_r = lane & 15, a_k = (lane >> 4) * 8;
    const int b_r = ((lane >> 4) << 3) + (lane & 7), b_k = ((lane >> 3) & 1) * 8;
    const uint32_t aOff = (uint32_t)((mBase + a_r) * SM_STRIDE + a_k) * 2;
    const uint32_t bOff = (uint32_t)(STAGE_A + ((nBase + b_r) * SM_STRIDE + b_k) * 2);

    const int nstages = K / 64;
    auto load_stage = [&](int s, int k0) {
        const uint32_t st = sbase + s * STAGE_SZ;
#pragma unroll
        for (int i = tid; i < 1536; i += 256) {
            const int which = (i >= 1024);
            const int idx = which ? (i - 1024) : i;
            const int row = idx >> 3, q = (idx & 7) * 8;
            const uint32_t dst = st + which * STAGE_A + (uint32_t)(row * SM_STRIDE + q) * 2;
            const __nv_bfloat16* src = which ? (Bg + (size_t)row * ldb + k0 + q)
                                             : (Ag + (size_t)row * lda + k0 + q);
            CP16(dst, src);
        }
    };

    load_stage(0, 0);
    CP_COMMIT();
    int cur = 0;
    for (int s = 1; s <= nstages; s++) {
        CP_WAIT0();
        __syncthreads();
        if (s < nstages) { load_stage(cur ^ 1, s * 64); CP_COMMIT(); }
        const uint32_t stA = sbase + cur * STAGE_SZ + aOff;
        const uint32_t stB = sbase + cur * STAGE_SZ + bOff;
#pragma unroll
        for (int kk = 0; kk < 4; kk++) {
            uint32_t af[4][4], bf[4];
#pragma unroll
            for (int mf = 0; mf < 4; mf++)
                ldsm4(stA + (uint32_t)(mf * 16 * SM_STRIDE + kk * 16) * 2,
                      af[mf][0], af[mf][1], af[mf][2], af[mf][3]);
            ldsm4(stB + (uint32_t)(kk * 16) * 2, bf[0], bf[1], bf[2], bf[3]);
#pragma unroll
            for (int mf = 0; mf < 4; mf++) {
                mma_bf16(acc[mf][0], af[mf][0], af[mf][1], af[mf][2], af[mf][3], bf[0], bf[1]);
                mma_bf16(acc[mf][1], af[mf][0], af[mf][1], af[mf][2], af[mf][3], bf[2], bf[3]);
            }
        }
        __syncthreads();
        cur ^= 1;
    }
}

__global__ __launch_bounds__(256) void k4(const float* __restrict__ x,
                                          const float* __restrict__ agg,
                                          float* __restrict__ out) {
    extern __shared__ __align__(16) char sm[];
    const int n0 = blockIdx.x * 128, c0 = blockIdx.y * 64;
    float acc[4][2][4] = {};
    gemm_pipe(g_fiT + (size_t)n0 * HS, HS, g_Tt + (size_t)c0 * HS, HS, HS, acc, sm);

    const int tid = threadIdx.x, lane = tid & 31, wid = tid >> 5;
    const int mBase = (wid >> 2) * 64, nBase = (wid & 3) * 16;
    const int r = lane >> 2, cc = (lane & 3) * 2;

    float* smf = (float*)sm;
#pragma unroll
    for (int mf = 0; mf < 4; mf++)
#pragma unroll
        for (int e = 0; e < 2; e++) {
            const int nl = mBase + mf * 16 + r + e * 8;
#pragma unroll
            for (int nf = 0; nf < 2; nf++) {
                const int cl = nBase + nf * 8 + cc;
                smf[(cl + 0) * EPS + nl] = acc[mf][nf][e * 2];
                smf[(cl + 1) * EPS + nl] = acc[mf][nf][e * 2 + 1];
            }
        }
    __syncthreads();

    const float scale = agg[0] * (1.0f / (float)NN);
#pragma unroll
    for (int t = tid; t < 2048; t += 256) {
        const int row = t >> 5, col = (t & 31) * 4;
        float4 v = *(float4*)(smf + row * EPS + col);
        const size_t gi = (size_t)(c0 + row) * NN + n0 + col;
        float4 xv = *(const float4*)(x + gi);
        v.x = xv.x + scale * v.x;  v.y = xv.y + scale * v.y;
        v.z = xv.z + scale * v.z;  v.w = xv.w + scale * v.w;
        *(float4*)(out + gi) = v;
    }
}

// ======================= launch =======================
extern "C" void kernel_launch(void* const* d_in, const int* in_sizes, int n_in,
                              void* d_out, int out_size) {
    const float* features = (const float*)d_in[0];
    const float* Wi       = (const float*)d_in[1];
    const float* bi       = (const float*)d_in[2];
    const float* Wj       = (const float*)d_in[3];
    const float* bj       = (const float*)d_in[4];
    const float* agg      = (const float*)d_in[5];
    float* out = (float*)d_out;

    cudaFuncSetAttribute(kA, cudaFuncAttributeMaxDynamicSharedMemorySize, KA_SMEM);
    cudaFuncSetAttribute(k4, cudaFuncAttributeMaxDynamicSharedMemorySize, SMEM_TOT);

    k0_w<<<512, 256>>>(Wi, Wj);
    kA<<<NSPL, 256, KA_SMEM>>>(features, bi, bj);
    kred<<<32, 256>>>();
    k4<<<dim3(81, 8), 256, SMEM_TOT>>>(features, agg, out);
}

// round 15
// speedup vs baseline: 1.1684x; 1.1684x over previous
#include <cuda_runtime.h>
#include <cuda_bf16.h>
#include <cstdint>

#define NN   10368
#define CC   512
#define HS   128
#define SPL  81            // n-chunks for T partials
#define NCHK 128           // n per k2 chunk

// ---------------- device scratch ----------------
__device__ __nv_bfloat16 g_Wcat[256 * CC];            // [256][512] K-major
__device__ __nv_bfloat16 g_fiT[NN * HS];              // fi^T [n][h]
__device__ __nv_bfloat16 g_fj[HS * NN];               // fj [h][n]
__device__ __nv_bfloat16 g_Tp[SPL * HS * CC];         // bf16 T partials [sp][h][c]
__device__ __nv_bfloat16 g_Tt[CC * HS];               // T^T [c][h]

// ---------------- helpers ----------------
__device__ __forceinline__ uint32_t smem_u32(const void* p) {
    uint32_t a;
    asm("{ .reg .u64 t; cvta.to.shared.u64 t, %1; cvt.u32.u64 %0, t; }" : "=r"(a) : "l"(p));
    return a;
}
__device__ __forceinline__ void ldsm4(uint32_t addr, uint32_t& r0, uint32_t& r1,
                                      uint32_t& r2, uint32_t& r3) {
    asm volatile("ldmatrix.sync.aligned.m8n8.x4.shared.b16 {%0,%1,%2,%3}, [%4];"
                 : "=r"(r0), "=r"(r1), "=r"(r2), "=r"(r3) : "r"(addr));
}
__device__ __forceinline__ void ldsm4t(uint32_t addr, uint32_t& r0, uint32_t& r1,
                                       uint32_t& r2, uint32_t& r3) {
    asm volatile("ldmatrix.sync.aligned.m8n8.x4.trans.shared.b16 {%0,%1,%2,%3}, [%4];"
                 : "=r"(r0), "=r"(r1), "=r"(r2), "=r"(r3) : "r"(addr));
}
__device__ __forceinline__ void mma_bf16(float* c, uint32_t a0, uint32_t a1, uint32_t a2,
                                         uint32_t a3, uint32_t b0, uint32_t b1) {
    asm volatile("mma.sync.aligned.m16n8k16.row.col.f32.bf16.bf16.f32 "
                 "{%0,%1,%2,%3}, {%4,%5,%6,%7}, {%8,%9}, {%0,%1,%2,%3};"
                 : "+f"(c[0]), "+f"(c[1]), "+f"(c[2]), "+f"(c[3])
                 : "r"(a0), "r"(a1), "r"(a2), "r"(a3), "r"(b0), "r"(b1));
}
#define CP16(dst, src)  asm volatile("cp.async.cg.shared.global [%0], [%1], 16;" :: "r"(dst), "l"(src))
#define CP_COMMIT()     asm volatile("cp.async.commit_group;" ::: "memory")
#define CP_WAIT0()      asm volatile("cp.async.wait_group 0;" ::: "memory")
#define CP_WAIT1()      asm volatile("cp.async.wait_group 1;" ::: "memory")

#define XBS  72            // bf16 smem row stride
#define FIS  136           // fi staging stride (bf16)

// ---- shared smem layout for k1/k2 (bytes) ----
#define A_OFF   0                      // A bf16 stages x2: [128][72]x2B = 18432 each
#define A_ST    18432
#define XF_OFF  36864                  // x fp32 stages x2: [64][64]x4B = 16384 each
#define XF_ST   16384
#define XC_OFF  69632                  // converted bf16 chunk [64][72]x2B = 9216
#define K_SMEM  78848

// ======================= k1: f = Wcat @ x, fused convert =======================
// grid (162, 2): n0 = bx*64, m0 = by*128.  K = 512 (8 chunks of 64).
__global__ __launch_bounds__(256) void k1(const float* __restrict__ x,
                                          const float* __restrict__ bi,
                                          const float* __restrict__ bj) {
    extern __shared__ __align__(16) char sm[];
    const uint32_t sb = smem_u32(sm);
    const int tid = threadIdx.x, lane = tid & 31, wid = tid >> 5;
    const int n0 = blockIdx.x * 64, m0 = blockIdx.y * 128;

    const int mBase = (wid >> 1) * 32, nB1 = (wid & 1) * 32;   // warp 32m x 32n
    float acc[2][4][4] = {};

    auto cpA = [&](int s) {        // Wcat [m0..m0+128), k chunk s
        const uint32_t st = sb + A_OFF + (s & 1) * A_ST;
#pragma unroll
        for (int i = tid; i < 1024; i += 256) {
            const int row = i >> 3, q = (i & 7) * 8;
            CP16(st + (uint32_t)(row * XBS + q) * 2,
                 g_Wcat + (size_t)(m0 + row) * CC + s * 64 + q);
        }
    };
    auto cpX = [&](int s) {        // x fp32 [s*64..+64 c rows][n0..n0+64]
        const uint32_t st = sb + XF_OFF + (s & 1) * XF_ST;
#pragma unroll
        for (int i = tid; i < 1024; i += 256) {
            const int c = i >> 4, q = (i & 15) * 4;
            CP16(st + (uint32_t)(c * 64 + q) * 4, x + (size_t)(s * 64 + c) * NN + n0 + q);
        }
    };

    cpA(0); cpX(0); CP_COMMIT();
    for (int s = 0; s < 8; s++) {
        if (s < 7) { cpA(s + 1); cpX(s + 1); CP_COMMIT(); CP_WAIT1(); }
        else       { CP_WAIT0(); }
        __syncthreads();
        {   // convert fp32 chunk -> bf16 [64 k-rows][72]
            const float* xs = (const float*)(sm + XF_OFF + (s & 1) * XF_ST);
            __nv_bfloat16* xc = (__nv_bfloat16*)(sm + XC_OFF);
#pragma unroll
            for (int i = tid; i < 512; i += 256) {
                const int c = i >> 3, q = (i & 7) * 8;
                float4 v0 = *(const float4*)(xs + c * 64 + q);
                float4 v1 = *(const float4*)(xs + c * 64 + q + 4);
                uint4 o; __nv_bfloat162 h;
                h = __floats2bfloat162_rn(v0.x, v0.y); o.x = *(uint32_t*)&h;
                h = __floats2bfloat162_rn(v0.z, v0.w); o.y = *(uint32_t*)&h;
                h = __floats2bfloat162_rn(v1.x, v1.y); o.z = *(uint32_t*)&h;
                h = __floats2bfloat162_rn(v1.z, v1.w); o.w = *(uint32_t*)&h;
                *(uint4*)(xc + (size_t)c * XBS + q) = o;
            }
        }
        __syncthreads();
        const uint32_t stA = sb + A_OFF + (s & 1) * A_ST;
#pragma unroll
        for (int kk = 0; kk < 4; kk++) {
            uint32_t af[2][4], bf[2][4];
#pragma unroll
            for (int mf = 0; mf < 2; mf++)
                ldsm4(stA + (uint32_t)((mBase + mf * 16 + (lane & 15)) * XBS
                                       + kk * 16 + (lane >> 4) * 8) * 2,
                      af[mf][0], af[mf][1], af[mf][2], af[mf][3]);
            // B trans: validated group order (R14)
#pragma unroll
            for (int nt = 0; nt < 2; nt++) {
                const int crow = kk * 16 + (lane & 7) + (((lane >> 3) & 1) << 3);
                const int ncol = nB1 + nt * 16 + ((lane >> 4) << 3);
                ldsm4t(sb + XC_OFF + (uint32_t)(crow * XBS + ncol) * 2,
                       bf[nt][0], bf[nt][1], bf[nt][2], bf[nt][3]);
            }
#pragma unroll
            for (int mf = 0; mf < 2; mf++)
#pragma unroll
                for (int nq = 0; nq < 2; nq++) {
                    mma_bf16(acc[mf][nq * 2],     af[mf][0], af[mf][1], af[mf][2], af[mf][3],
                             bf[nq][0], bf[nq][1]);
                    mma_bf16(acc[mf][nq * 2 + 1], af[mf][0], af[mf][1], af[mf][2], af[mf][3],
                             bf[nq][2], bf[nq][3]);
                }
        }
        __syncthreads();   // mma done before next convert overwrites XC
    }

    // ---- epilogue: stage + coalesced flush ----
    const int r = lane >> 2, cc2 = (lane & 3) * 2;
    if (m0 == 0) {   // fi -> transposed staging [64 n][136]
        __nv_bfloat16* fiS = (__nv_bfloat16*)(sm + A_OFF);
#pragma unroll
        for (int mf = 0; mf < 2; mf++)
#pragma unroll
            for (int e = 0; e < 2; e++) {
                const int m = mBase + mf * 16 + r + e * 8;
                const float bias = bi[m];
#pragma unroll
                for (int nf = 0; nf < 4; nf++) {
                    const int nl = nB1 + nf * 8 + cc2;
                    fiS[(nl + 0) * FIS + m] = __float2bfloat16(acc[mf][nf][e * 2] + bias);
                    fiS[(nl + 1) * FIS + m] = __float2bfloat16(acc[mf][nf][e * 2 + 1] + bias);
                }
            }
        __syncthreads();
#pragma unroll
        for (int i = tid; i < 1024; i += 256) {
            const int row = i >> 4, q = (i & 15) * 8;
            *(uint4*)(g_fiT + (size_t)(n0 + row) * HS + q) = *(uint4*)(fiS + row * FIS + q);
        }
    } else {         // fj -> row-major staging [128 h][72]
        __nv_bfloat16* fjS = (__nv_bfloat16*)(sm + A_OFF);
#pragma unroll
        for (int mf = 0; mf < 2; mf++)
#pragma unroll
            for (int e = 0; e < 2; e++) {
                const int hh = mBase + mf * 16 + r + e * 8;
                const float bias = bj[hh];
#pragma unroll
                for (int nf = 0; nf < 4; nf++) {
                    const int nl = nB1 + nf * 8 + cc2;
                    *(__nv_bfloat162*)(fjS + hh * XBS + nl) =
                        __floats2bfloat162_rn(acc[mf][nf][e * 2] + bias,
                                              acc[mf][nf][e * 2 + 1] + bias);
                }
            }
        __syncthreads();
#pragma unroll
        for (int i = tid; i < 1024; i += 256) {
            const int row = i >> 3, q = (i & 7) * 8;
            *(uint4*)(g_fj + (size_t)row * NN + n0 + q) = *(uint4*)(fjS + row * XBS + q);
        }
    }
}

// ======================= k2: Tp[sp] = fj @ x^T, fused convert =======================
// grid (8, 81): c0 = bx*64, chunk sp = by (128 n).  K = 128 (2 chunks of 64).
__global__ __launch_bounds__(256) void k2(const float* __restrict__ x) {
    extern __shared__ __align__(16) char sm[];
    const uint32_t sb = smem_u32(sm);
    const int tid = threadIdx.x, lane = tid & 31, wid = tid >> 5;
    const int c0 = blockIdx.x * 64, nb = blockIdx.y * NCHK;

    const int mBase = (wid >> 1) * 32, cB = (wid & 1) * 32;    // warp 32h x 32c
    float acc[2][4][4] = {};

    auto cpA = [&](int s) {        // fj [128 h][64 n chunk]
        const uint32_t st = sb + A_OFF + (s & 1) * A_ST;
#pragma unroll
        for (int i = tid; i < 1024; i += 256) {
            const int row = i >> 3, q = (i & 7) * 8;
            CP16(st + (uint32_t)(row * XBS + q) * 2,
                 g_fj + (size_t)row * NN + nb + s * 64 + q);
        }
    };
    auto cpX = [&](int s) {        // x fp32 [c0..+64 rows][nb+s*64 ..+64]
        const uint32_t st = sb + XF_OFF + (s & 1) * XF_ST;
#pragma unroll
        for (int i = tid; i < 1024; i += 256) {
            const int c = i >> 4, q = (i & 15) * 4;
            CP16(st + (uint32_t)(c * 64 + q) * 4,
                 x + (size_t)(c0 + c) * NN + nb + s * 64 + q);
        }
    };

    cpA(0); cpX(0); CP_COMMIT();
    for (int s = 0; s < 2; s++) {
        if (s < 1) { cpA(1); cpX(1); CP_COMMIT(); CP_WAIT1(); }
        else       { CP_WAIT0(); }
        __syncthreads();
        {   // convert fp32 chunk -> bf16 [64 c-rows][72] (k=n contiguous)
            const float* xs = (const float*)(sm + XF_OFF + (s & 1) * XF_ST);
            __nv_bfloat16* xc = (__nv_bfloat16*)(sm + XC_OFF);
#pragma unroll
            for (int i = tid; i < 512; i += 256) {
                const int c = i >> 3, q = (i & 7) * 8;
                float4 v0 = *(const float4*)(xs + c * 64 + q);
                float4 v1 = *(const float4*)(xs + c * 64 + q + 4);
                uint4 o; __nv_bfloat162 h;
                h = __floats2bfloat162_rn(v0.x, v0.y); o.x = *(uint32_t*)&h;
                h = __floats2bfloat162_rn(v0.z, v0.w); o.y = *(uint32_t*)&h;
                h = __floats2bfloat162_rn(v1.x, v1.y); o.z = *(uint32_t*)&h;
                h = __floats2bfloat162_rn(v1.z, v1.w); o.w = *(uint32_t*)&h;
                *(uint4*)(xc + (size_t)c * XBS + q) = o;
            }
        }
        __syncthreads();
        const uint32_t stA = sb + A_OFF + (s & 1) * A_ST;
        const int b_r = ((lane >> 4) << 3) + (lane & 7), b_k = ((lane >> 3) & 1) * 8;
#pragma unroll
        for (int kk = 0; kk < 4; kk++) {
            uint32_t af[2][4], bf[2][4];
#pragma unroll
            for (int mf = 0; mf < 2; mf++)
                ldsm4(stA + (uint32_t)((mBase + mf * 16 + (lane & 15)) * XBS
                                       + kk * 16 + (lane >> 4) * 8) * 2,
                      af[mf][0], af[mf][1], af[mf][2], af[mf][3]);
#pragma unroll
            for (int nq = 0; nq < 2; nq++)
                ldsm4(sb + XC_OFF + (uint32_t)((cB + nq * 16 + b_r) * XBS
                                               + kk * 16 + b_k) * 2,
                      bf[nq][0], bf[nq][1], bf[nq][2], bf[nq][3]);
#pragma unroll
            for (int mf = 0; mf < 2; mf++)
#pragma unroll
                for (int nq = 0; nq < 2; nq++) {
                    mma_bf16(acc[mf][nq * 2],     af[mf][0], af[mf][1], af[mf][2], af[mf][3],
                             bf[nq][0], bf[nq][1]);
                    mma_bf16(acc[mf][nq * 2 + 1], af[mf][0], af[mf][1], af[mf][2], af[mf][3],
                             bf[nq][2], bf[nq][3]);
                }
        }
        __syncthreads();
    }

    // ---- epilogue: stage [128 h][72] bf16, coalesced flush to Tp ----
    __nv_bfloat16* tS = (__nv_bfloat16*)(sm + A_OFF);
    const int r = lane >> 2, cc2 = (lane & 3) * 2;
#pragma unroll
    for (int mf = 0; mf < 2; mf++)
#pragma unroll
        for (int e = 0; e < 2; e++) {
            const int hh = mBase + mf * 16 + r + e * 8;
#pragma unroll
            for (int nf = 0; nf < 4; nf++) {
                const int cl = cB + nf * 8 + cc2;
                *(__nv_bfloat162*)(tS + hh * XBS + cl) =
                    __floats2bfloat162_rn(acc[mf][nf][e * 2], acc[mf][nf][e * 2 + 1]);
            }
        }
    __syncthreads();
    __nv_bfloat16* dst = g_Tp + (size_t)blockIdx.y * HS * CC + c0;
#pragma unroll
    for (int i = tid; i < 1024; i += 256) {
        const int row = i >> 3, q = (i & 7) * 8;
        *(uint4*)(dst + (size_t)row * CC + q) = *(uint4*)(tS + row * XBS + q);
    }
}

// ======================= k0: weights -> bf16 concat =======================
__global__ void k0_w(const float* __restrict__ Wi, const float* __restrict__ Wj) {
    int i = blockIdx.x * 256 + threadIdx.x;
    if (i < 256 * CC)
        g_Wcat[i] = __float2bfloat16(i < HS * CC ? Wi[i] : Wj[i - HS * CC]);
}

// ======================= kred: Tt[c][h] = bf16(sum_sp Tp) =======================
__global__ void kred() {
    const int idx = blockIdx.x * 256 + threadIdx.x;       // 8192 threads
    const int i8 = idx * 8;
    const int h = i8 >> 9, c0 = i8 & 511;
    float s[8] = {};
    for (int p = 0; p < SPL; p++) {
        uint4 v = *(const uint4*)(g_Tp + (size_t)p * HS * CC + h * CC + c0);
        const __nv_bfloat162* b = (const __nv_bfloat162*)&v;
#pragma unroll
        for (int j = 0; j < 4; j++) {
            float2 f = __bfloat1622float2(b[j]);
            s[2 * j] += f.x; s[2 * j + 1] += f.y;
        }
    }
#pragma unroll
    for (int j = 0; j < 8; j++)
        g_Tt[(size_t)(c0 + j) * HS + h] = __float2bfloat16(s[j]);
}

// ======================= k4: out = x + scale * (fiT @ Tt^T)^T =======================
#define SM_STRIDE 72
#define STAGE_A   (128 * SM_STRIDE * 2)
#define STAGE_B   (64 * SM_STRIDE * 2)
#define STAGE_SZ  (STAGE_A + STAGE_B)
#define SMEM_TOT  (2 * STAGE_SZ)
#define EPS 132

__device__ __forceinline__ void gemm_pipe(const __nv_bfloat16* __restrict__ Ag, size_t lda,
                                          const __nv_bfloat16* __restrict__ Bg, size_t ldb,
                                          int K, float acc[4][2][4], char* sm) {
    const int tid = threadIdx.x, lane = tid & 31, wid = tid >> 5;
    const int mBase = (wid >> 2) * 64, nBase = (wid & 3) * 16;
    const uint32_t sbase = smem_u32(sm);

    const int a_r = lane & 15, a_k = (lane >> 4) * 8;
    const int b_r = ((lane >> 4) << 3) + (lane & 7), b_k = ((lane >> 3) & 1) * 8;
    const uint32_t aOff = (uint32_t)((mBase + a_r) * SM_STRIDE + a_k) * 2;
    const uint32_t bOff = (uint32_t)(STAGE_A + ((nBase + b_r) * SM_STRIDE + b_k) * 2);

    const int nstages = K / 64;
    auto load_stage = [&](int s, int k0) {
        const uint32_t st = sbase + s * STAGE_SZ;
#pragma unroll
        for (int i = tid; i < 1536; i += 256) {
            const int which = (i >= 1024);
            const int idx = which ? (i - 1024) : i;
            const int row = idx >> 3, q = (idx & 7) * 8;
            const uint32_t dst = st + which * STAGE_A + (uint32_t)(row * SM_STRIDE + q) * 2;
            const __nv_bfloat16* src = which ? (Bg + (size_t)row * ldb + k0 + q)
                                             : (Ag + (size_t)row * lda + k0 + q);
            CP16(dst, src);
        }
    };

    load_stage(0, 0);
    CP_COMMIT();
    int cur = 0;
    for (int s = 1; s <= nstages; s++) {
        CP_WAIT0();
        __syncthreads();
        if (s < nstages) { load_stage(cur ^ 1, s * 64); CP_COMMIT(); }
        const uint32_t stA = sbase + cur * STAGE_SZ + aOff;
        const uint32_t stB = sbase + cur * STAGE_SZ + bOff;
#pragma unroll
        for (int kk = 0; kk < 4; kk++) {
            uint32_t af[4][4], bf[4];
#pragma unroll
            for (int mf = 0; mf < 4; mf++)
                ldsm4(stA + (uint32_t)(mf * 16 * SM_STRIDE + kk * 16) * 2,
                      af[mf][0], af[mf][1], af[mf][2], af[mf][3]);
            ldsm4(stB + (uint32_t)(kk * 16) * 2, bf[0], bf[1], bf[2], bf[3]);
#pragma unroll
            for (int mf = 0; mf < 4; mf++) {
                mma_bf16(acc[mf][0], af[mf][0], af[mf][1], af[mf][2], af[mf][3], bf[0], bf[1]);
                mma_bf16(acc[mf][1], af[mf][0], af[mf][1], af[mf][2], af[mf][3], bf[2], bf[3]);
            }
        }
        __syncthreads();
        cur ^= 1;
    }
}

__global__ __launch_bounds__(256) void k4(const float* __restrict__ x,
                                          const float* __restrict__ agg,
                                          float* __restrict__ out) {
    extern __shared__ __align__(16) char sm[];
    const int n0 = blockIdx.x * 128, c0 = blockIdx.y * 64;
    float acc[4][2][4] = {};
    gemm_pipe(g_fiT + (size_t)n0 * HS, HS, g_Tt + (size_t)c0 * HS, HS, HS, acc, sm);

    const int tid = threadIdx.x, lane = tid & 31, wid = tid >> 5;
    const int mBase = (wid >> 2) * 64, nBase = (wid & 3) * 16;
    const int r = lane >> 2, cc = (lane & 3) * 2;

    float* smf = (float*)sm;
#pragma unroll
    for (int mf = 0; mf < 4; mf++)
#pragma unroll
        for (int e = 0; e < 2; e++) {
            const int nl = mBase + mf * 16 + r + e * 8;
#pragma unroll
            for (int nf = 0; nf < 2; nf++) {
                const int cl = nBase + nf * 8 + cc;
                smf[(cl + 0) * EPS + nl] = acc[mf][nf][e * 2];
                smf[(cl + 1) * EPS + nl] = acc[mf][nf][e * 2 + 1];
            }
        }
    __syncthreads();

    const float scale = agg[0] * (1.0f / (float)NN);
#pragma unroll
    for (int t = tid; t < 2048; t += 256) {
        const int row = t >> 5, col = (t & 31) * 4;
        float4 v = *(float4*)(smf + row * EPS + col);
        const size_t gi = (size_t)(c0 + row) * NN + n0 + col;
        float4 xv = *(const float4*)(x + gi);
        v.x = xv.x + scale * v.x;  v.y = xv.y + scale * v.y;
        v.z = xv.z + scale * v.z;  v.w = xv.w + scale * v.w;
        *(float4*)(out + gi) = v;
    }
}

// ======================= launch =======================
extern "C" void kernel_launch(void* const* d_in, const int* in_sizes, int n_in,
                              void* d_out, int out_size) {
    const float* features = (const float*)d_in[0];
    const float* Wi       = (const float*)d_in[1];
    const float* bi       = (const float*)d_in[2];
    const float* Wj       = (const float*)d_in[3];
    const float* bj       = (const float*)d_in[4];
    const float* agg      = (const float*)d_in[5];
    float* out = (float*)d_out;

    cudaFuncSetAttribute(k1, cudaFuncAttributeMaxDynamicSharedMemorySize, K_SMEM);
    cudaFuncSetAttribute(k2, cudaFuncAttributeMaxDynamicSharedMemorySize, K_SMEM);
    cudaFuncSetAttribute(k4, cudaFuncAttributeMaxDynamicSharedMemorySize, SMEM_TOT);

    k0_w<<<512, 256>>>(Wi, Wj);
    k1<<<dim3(162, 2), 256, K_SMEM>>>(features, bi, bj);
    k2<<<dim3(8, SPL), 256, K_SMEM>>>(features);
    kred<<<32, 256>>>();
    k4<<<dim3(81, 8), 256, SMEM_TOT>>>(features, agg, out);
}

// round 16
// speedup vs baseline: 1.2477x; 1.0679x over previous
#include <cuda_runtime.h>
#include <cuda_bf16.h>
#include <cstdint>

#define NN   10368
#define CC   512
#define HS   128
#define SPL  81            // n-chunks for T partials
#define NCHK 128           // n per k2 chunk
#define RG   9             // reduction groups (SPL = RG*RG)

// ---------------- device scratch ----------------
__device__ __nv_bfloat16 g_Wcat[256 * CC];            // [256][512] K-major
__device__ __nv_bfloat16 g_fiT[NN * HS];              // fi^T [n][h]
__device__ __nv_bfloat16 g_fj[HS * NN];               // fj [h][n]
__device__ __nv_bfloat16 g_Tp[SPL * HS * CC];         // bf16 T partials [sp][h][c]
__device__ float         g_Tr[RG * HS * CC];          // stage-1 fp32 partials
__device__ __nv_bfloat16 g_Tt[CC * HS];               // T^T [c][h]

// ---------------- helpers ----------------
__device__ __forceinline__ uint32_t smem_u32(const void* p) {
    uint32_t a;
    asm("{ .reg .u64 t; cvta.to.shared.u64 t, %1; cvt.u32.u64 %0, t; }" : "=r"(a) : "l"(p));
    return a;
}
__device__ __forceinline__ void ldsm4(uint32_t addr, uint32_t& r0, uint32_t& r1,
                                      uint32_t& r2, uint32_t& r3) {
    asm volatile("ldmatrix.sync.aligned.m8n8.x4.shared.b16 {%0,%1,%2,%3}, [%4];"
                 : "=r"(r0), "=r"(r1), "=r"(r2), "=r"(r3) : "r"(addr));
}
__device__ __forceinline__ void ldsm4t(uint32_t addr, uint32_t& r0, uint32_t& r1,
                                       uint32_t& r2, uint32_t& r3) {
    asm volatile("ldmatrix.sync.aligned.m8n8.x4.trans.shared.b16 {%0,%1,%2,%3}, [%4];"
                 : "=r"(r0), "=r"(r1), "=r"(r2), "=r"(r3) : "r"(addr));
}
__device__ __forceinline__ void mma_bf16(float* c, uint32_t a0, uint32_t a1, uint32_t a2,
                                         uint32_t a3, uint32_t b0, uint32_t b1) {
    asm volatile("mma.sync.aligned.m16n8k16.row.col.f32.bf16.bf16.f32 "
                 "{%0,%1,%2,%3}, {%4,%5,%6,%7}, {%8,%9}, {%0,%1,%2,%3};"
                 : "+f"(c[0]), "+f"(c[1]), "+f"(c[2]), "+f"(c[3])
                 : "r"(a0), "r"(a1), "r"(a2), "r"(a3), "r"(b0), "r"(b1));
}
#define CP16(dst, src)  asm volatile("cp.async.cg.shared.global [%0], [%1], 16;" :: "r"(dst), "l"(src))
#define CP_COMMIT()     asm volatile("cp.async.commit_group;" ::: "memory")
#define CP_WAIT0()      asm volatile("cp.async.wait_group 0;" ::: "memory")
#define CP_WAIT1()      asm volatile("cp.async.wait_group 1;" ::: "memory")

#define XBS  72            // bf16 smem row stride
#define FIS  136           // fi staging stride (bf16)

// ---- shared smem layout for k1/k2 (bytes) ----
#define A_OFF   0
#define A_ST    18432
#define XF_OFF  36864
#define XF_ST   16384
#define XC_OFF  69632
#define K_SMEM  78848

// ======================= k1: f = Wcat @ x, fused convert =======================
__global__ __launch_bounds__(256) void k1(const float* __restrict__ x,
                                          const float* __restrict__ bi,
                                          const float* __restrict__ bj) {
    extern __shared__ __align__(16) char sm[];
    const uint32_t sb = smem_u32(sm);
    const int tid = threadIdx.x, lane = tid & 31, wid = tid >> 5;
    const int n0 = blockIdx.x * 64, m0 = blockIdx.y * 128;

    const int mBase = (wid >> 1) * 32, nB1 = (wid & 1) * 32;
    float acc[2][4][4] = {};

    auto cpA = [&](int s) {
        const uint32_t st = sb + A_OFF + (s & 1) * A_ST;
#pragma unroll
        for (int i = tid; i < 1024; i += 256) {
            const int row = i >> 3, q = (i & 7) * 8;
            CP16(st + (uint32_t)(row * XBS + q) * 2,
                 g_Wcat + (size_t)(m0 + row) * CC + s * 64 + q);
        }
    };
    auto cpX = [&](int s) {
        const uint32_t st = sb + XF_OFF + (s & 1) * XF_ST;
#pragma unroll
        for (int i = tid; i < 1024; i += 256) {
            const int c = i >> 4, q = (i & 15) * 4;
            CP16(st + (uint32_t)(c * 64 + q) * 4, x + (size_t)(s * 64 + c) * NN + n0 + q);
        }
    };

    cpA(0); cpX(0); CP_COMMIT();
    for (int s = 0; s < 8; s++) {
        if (s < 7) { cpA(s + 1); cpX(s + 1); CP_COMMIT(); CP_WAIT1(); }
        else       { CP_WAIT0(); }
        __syncthreads();
        {
            const float* xs = (const float*)(sm + XF_OFF + (s & 1) * XF_ST);
            __nv_bfloat16* xc = (__nv_bfloat16*)(sm + XC_OFF);
#pragma unroll
            for (int i = tid; i < 512; i += 256) {
                const int c = i >> 3, q = (i & 7) * 8;
                float4 v0 = *(const float4*)(xs + c * 64 + q);
                float4 v1 = *(const float4*)(xs + c * 64 + q + 4);
                uint4 o; __nv_bfloat162 h;
                h = __floats2bfloat162_rn(v0.x, v0.y); o.x = *(uint32_t*)&h;
                h = __floats2bfloat162_rn(v0.z, v0.w); o.y = *(uint32_t*)&h;
                h = __floats2bfloat162_rn(v1.x, v1.y); o.z = *(uint32_t*)&h;
                h = __floats2bfloat162_rn(v1.z, v1.w); o.w = *(uint32_t*)&h;
                *(uint4*)(xc + (size_t)c * XBS + q) = o;
            }
        }
        __syncthreads();
        const uint32_t stA = sb + A_OFF + (s & 1) * A_ST;
#pragma unroll
        for (int kk = 0; kk < 4; kk++) {
            uint32_t af[2][4], bf[2][4];
#pragma unroll
            for (int mf = 0; mf < 2; mf++)
                ldsm4(stA + (uint32_t)((mBase + mf * 16 + (lane & 15)) * XBS
                                       + kk * 16 + (lane >> 4) * 8) * 2,
                      af[mf][0], af[mf][1], af[mf][2], af[mf][3]);
#pragma unroll
            for (int nt = 0; nt < 2; nt++) {
                const int crow = kk * 16 + (lane & 7) + (((lane >> 3) & 1) << 3);
                const int ncol = nB1 + nt * 16 + ((lane >> 4) << 3);
                ldsm4t(sb + XC_OFF + (uint32_t)(crow * XBS + ncol) * 2,
                       bf[nt][0], bf[nt][1], bf[nt][2], bf[nt][3]);
            }
#pragma unroll
            for (int mf = 0; mf < 2; mf++)
#pragma unroll
                for (int nq = 0; nq < 2; nq++) {
                    mma_bf16(acc[mf][nq * 2],     af[mf][0], af[mf][1], af[mf][2], af[mf][3],
                             bf[nq][0], bf[nq][1]);
                    mma_bf16(acc[mf][nq * 2 + 1], af[mf][0], af[mf][1], af[mf][2], af[mf][3],
                             bf[nq][2], bf[nq][3]);
                }
        }
        __syncthreads();
    }

    const int r = lane >> 2, cc2 = (lane & 3) * 2;
    if (m0 == 0) {
        __nv_bfloat16* fiS = (__nv_bfloat16*)(sm + A_OFF);
#pragma unroll
        for (int mf = 0; mf < 2; mf++)
#pragma unroll
            for (int e = 0; e < 2; e++) {
                const int m = mBase + mf * 16 + r + e * 8;
                const float bias = bi[m];
#pragma unroll
                for (int nf = 0; nf < 4; nf++) {
                    const int nl = nB1 + nf * 8 + cc2;
                    fiS[(nl + 0) * FIS + m] = __float2bfloat16(acc[mf][nf][e * 2] + bias);
                    fiS[(nl + 1) * FIS + m] = __float2bfloat16(acc[mf][nf][e * 2 + 1] + bias);
                }
            }
        __syncthreads();
#pragma unroll
        for (int i = tid; i < 1024; i += 256) {
            const int row = i >> 4, q = (i & 15) * 8;
            *(uint4*)(g_fiT + (size_t)(n0 + row) * HS + q) = *(uint4*)(fiS + row * FIS + q);
        }
    } else {
        __nv_bfloat16* fjS = (__nv_bfloat16*)(sm + A_OFF);
#pragma unroll
        for (int mf = 0; mf < 2; mf++)
#pragma unroll
            for (int e = 0; e < 2; e++) {
                const int hh = mBase + mf * 16 + r + e * 8;
                const float bias = bj[hh];
#pragma unroll
                for (int nf = 0; nf < 4; nf++) {
                    const int nl = nB1 + nf * 8 + cc2;
                    *(__nv_bfloat162*)(fjS + hh * XBS + nl) =
                        __floats2bfloat162_rn(acc[mf][nf][e * 2] + bias,
                                              acc[mf][nf][e * 2 + 1] + bias);
                }
            }
        __syncthreads();
#pragma unroll
        for (int i = tid; i < 1024; i += 256) {
            const int row = i >> 3, q = (i & 7) * 8;
            *(uint4*)(g_fj + (size_t)row * NN + n0 + q) = *(uint4*)(fjS + row * XBS + q);
        }
    }
}

// ======================= k2: Tp[sp] = fj @ x^T, fused convert =======================
__global__ __launch_bounds__(256) void k2(const float* __restrict__ x) {
    extern __shared__ __align__(16) char sm[];
    const uint32_t sb = smem_u32(sm);
    const int tid = threadIdx.x, lane = tid & 31, wid = tid >> 5;
    const int c0 = blockIdx.x * 64, nb = blockIdx.y * NCHK;

    const int mBase = (wid >> 1) * 32, cB = (wid & 1) * 32;
    float acc[2][4][4] = {};

    auto cpA = [&](int s) {
        const uint32_t st = sb + A_OFF + (s & 1) * A_ST;
#pragma unroll
        for (int i = tid; i < 1024; i += 256) {
            const int row = i >> 3, q = (i & 7) * 8;
            CP16(st + (uint32_t)(row * XBS + q) * 2,
                 g_fj + (size_t)row * NN + nb + s * 64 + q);
        }
    };
    auto cpX = [&](int s) {
        const uint32_t st = sb + XF_OFF + (s & 1) * XF_ST;
#pragma unroll
        for (int i = tid; i < 1024; i += 256) {
            const int c = i >> 4, q = (i & 15) * 4;
            CP16(st + (uint32_t)(c * 64 + q) * 4,
                 x + (size_t)(c0 + c) * NN + nb + s * 64 + q);
        }
    };

    cpA(0); cpX(0); CP_COMMIT();
    for (int s = 0; s < 2; s++) {
        if (s < 1) { cpA(1); cpX(1); CP_COMMIT(); CP_WAIT1(); }
        else       { CP_WAIT0(); }
        __syncthreads();
        {
            const float* xs = (const float*)(sm + XF_OFF + (s & 1) * XF_ST);
            __nv_bfloat16* xc = (__nv_bfloat16*)(sm + XC_OFF);
#pragma unroll
            for (int i = tid; i < 512; i += 256) {
                const int c = i >> 3, q = (i & 7) * 8;
                float4 v0 = *(const float4*)(xs + c * 64 + q);
                float4 v1 = *(const float4*)(xs + c * 64 + q + 4);
                uint4 o; __nv_bfloat162 h;
                h = __floats2bfloat162_rn(v0.x, v0.y); o.x = *(uint32_t*)&h;
                h = __floats2bfloat162_rn(v0.z, v0.w); o.y = *(uint32_t*)&h;
                h = __floats2bfloat162_rn(v1.x, v1.y); o.z = *(uint32_t*)&h;
                h = __floats2bfloat162_rn(v1.z, v1.w); o.w = *(uint32_t*)&h;
                *(uint4*)(xc + (size_t)c * XBS + q) = o;
            }
        }
        __syncthreads();
        const uint32_t stA = sb + A_OFF + (s & 1) * A_ST;
        const int b_r = ((lane >> 4) << 3) + (lane & 7), b_k = ((lane >> 3) & 1) * 8;
#pragma unroll
        for (int kk = 0; kk < 4; kk++) {
            uint32_t af[2][4], bf[2][4];
#pragma unroll
            for (int mf = 0; mf < 2; mf++)
                ldsm4(stA + (uint32_t)((mBase + mf * 16 + (lane & 15)) * XBS
                                       + kk * 16 + (lane >> 4) * 8) * 2,
                      af[mf][0], af[mf][1], af[mf][2], af[mf][3]);
#pragma unroll
            for (int nq = 0; nq < 2; nq++)
                ldsm4(sb + XC_OFF + (uint32_t)((cB + nq * 16 + b_r) * XBS
                                               + kk * 16 + b_k) * 2,
                      bf[nq][0], bf[nq][1], bf[nq][2], bf[nq][3]);
#pragma unroll
            for (int mf = 0; mf < 2; mf++)
#pragma unroll
                for (int nq = 0; nq < 2; nq++) {
                    mma_bf16(acc[mf][nq * 2],     af[mf][0], af[mf][1], af[mf][2], af[mf][3],
                             bf[nq][0], bf[nq][1]);
                    mma_bf16(acc[mf][nq * 2 + 1], af[mf][0], af[mf][1], af[mf][2], af[mf][3],
                             bf[nq][2], bf[nq][3]);
                }
        }
        __syncthreads();
    }

    __nv_bfloat16* tS = (__nv_bfloat16*)(sm + A_OFF);
    const int r = lane >> 2, cc2 = (lane & 3) * 2;
#pragma unroll
    for (int mf = 0; mf < 2; mf++)
#pragma unroll
        for (int e = 0; e < 2; e++) {
            const int hh = mBase + mf * 16 + r + e * 8;
#pragma unroll
            for (int nf = 0; nf < 4; nf++) {
                const int cl = cB + nf * 8 + cc2;
                *(__nv_bfloat162*)(tS + hh * XBS + cl) =
                    __floats2bfloat162_rn(acc[mf][nf][e * 2], acc[mf][nf][e * 2 + 1]);
            }
        }
    __syncthreads();
    __nv_bfloat16* dst = g_Tp + (size_t)blockIdx.y * HS * CC + c0;
#pragma unroll
    for (int i = tid; i < 1024; i += 256) {
        const int row = i >> 3, q = (i & 7) * 8;
        *(uint4*)(dst + (size_t)row * CC + q) = *(uint4*)(tS + row * XBS + q);
    }
}

// ======================= k0: weights -> bf16 concat =======================
__global__ void k0_w(const float* __restrict__ Wi, const float* __restrict__ Wj) {
    int i = blockIdx.x * 256 + threadIdx.x;
    if (i < 256 * CC)
        g_Wcat[i] = __float2bfloat16(i < HS * CC ? Wi[i] : Wj[i - HS * CC]);
}

// ======================= kred1: stage-1 tree reduce (9 splits/group) =======================
// grid (32, 9), block 256
__global__ void kred1() {
    const int g = blockIdx.y;
    const int idx = blockIdx.x * 256 + threadIdx.x;       // 8192 per group
    const int i8 = idx * 8;                               // 8 bf16 = 16 B
    float s[8] = {};
#pragma unroll
    for (int pp = 0; pp < RG; pp++) {
        const int p = g * RG + pp;
        uint4 v = *(const uint4*)(g_Tp + (size_t)p * HS * CC + i8);
        const __nv_bfloat162* b = (const __nv_bfloat162*)&v;
#pragma unroll
        for (int j = 0; j < 4; j++) {
            float2 f = __bfloat1622float2(b[j]);
            s[2 * j] += f.x; s[2 * j + 1] += f.y;
        }
    }
    float4* dst = (float4*)(g_Tr + (size_t)g * HS * CC + i8);
    dst[0] = make_float4(s[0], s[1], s[2], s[3]);
    dst[1] = make_float4(s[4], s[5], s[6], s[7]);
}

// ======================= kred2: stage-2 reduce + transpose to Tt =======================
// grid 32, block 256
__global__ void kred2() {
    const int idx = blockIdx.x * 256 + threadIdx.x;
    const int i8 = idx * 8;
    const int h = i8 >> 9, c0 = i8 & 511;
    float s[8] = {};
#pragma unroll
    for (int g = 0; g < RG; g++) {
        const float4* src = (const float4*)(g_Tr + (size_t)g * HS * CC + i8);
        float4 v0 = src[0], v1 = src[1];
        s[0] += v0.x; s[1] += v0.y; s[2] += v0.z; s[3] += v0.w;
        s[4] += v1.x; s[5] += v1.y; s[6] += v1.z; s[7] += v1.w;
    }
#pragma unroll
    for (int j = 0; j < 8; j++)
        g_Tt[(size_t)(c0 + j) * HS + h] = __float2bfloat16(s[j]);
}

// ======================= k4: out = x + scale * (fiT @ Tt^T)^T =======================
#define SM_STRIDE 72
#define STAGE_A   (128 * SM_STRIDE * 2)
#define STAGE_B   (64 * SM_STRIDE * 2)
#define STAGE_SZ  (STAGE_A + STAGE_B)
#define SMEM_TOT  (2 * STAGE_SZ)
#define EPS 132

__device__ __forceinline__ void gemm_pipe(const __nv_bfloat16* __restrict__ Ag, size_t lda,
                                          const __nv_bfloat16* __restrict__ Bg, size_t ldb,
                                          int K, float acc[4][2][4], char* sm) {
    const int tid = threadIdx.x, lane = tid & 31, wid = tid >> 5;
    const int mBase = (wid >> 2) * 64, nBase = (wid & 3) * 16;
    const uint32_t sbase = smem_u32(sm);

    const int a_r = lane & 15, a_k = (lane >> 4) * 8;
    const int b_r = ((lane >> 4) << 3) + (lane & 7), b_k = ((lane >> 3) & 1) * 8;
    const uint32_t aOff = (uint32_t)((mBase + a_r) * SM_STRIDE + a_k) * 2;
    const uint32_t bOff = (uint32_t)(STAGE_A + ((nBase + b_r) * SM_STRIDE + b_k) * 2);

    const int nstages = K / 64;
    auto load_stage = [&](int s, int k0) {
        const uint32_t st = sbase + s * STAGE_SZ;
#pragma unroll
        for (int i = tid; i < 1536; i += 256) {
            const int which = (i >= 1024);
            const int idx = which ? (i - 1024) : i;
            const int row = idx >> 3, q = (idx & 7) * 8;
            const uint32_t dst = st + which * STAGE_A + (uint32_t)(row * SM_STRIDE + q) * 2;
            const __nv_bfloat16* src = which ? (Bg + (size_t)row * ldb + k0 + q)
                                             : (Ag + (size_t)row * lda + k0 + q);
            CP16(dst, src);
        }
    };

    load_stage(0, 0);
    CP_COMMIT();
    int cur = 0;
    for (int s = 1; s <= nstages; s++) {
        CP_WAIT0();
        __syncthreads();
        if (s < nstages) { load_stage(cur ^ 1, s * 64); CP_COMMIT(); }
        const uint32_t stA = sbase + cur * STAGE_SZ + aOff;
        const uint32_t stB = sbase + cur * STAGE_SZ + bOff;
#pragma unroll
        for (int kk = 0; kk < 4; kk++) {
            uint32_t af[4][4], bf[4];
#pragma unroll
            for (int mf = 0; mf < 4; mf++)
                ldsm4(stA + (uint32_t)(mf * 16 * SM_STRIDE + kk * 16) * 2,
                      af[mf][0], af[mf][1], af[mf][2], af[mf][3]);
            ldsm4(stB + (uint32_t)(kk * 16) * 2, bf[0], bf[1], bf[2], bf[3]);
#pragma unroll
            for (int mf = 0; mf < 4; mf++) {
                mma_bf16(acc[mf][0], af[mf][0], af[mf][1], af[mf][2], af[mf][3], bf[0], bf[1]);
                mma_bf16(acc[mf][1], af[mf][0], af[mf][1], af[mf][2], af[mf][3], bf[2], bf[3]);
            }
        }
        __syncthreads();
        cur ^= 1;
    }
}

__global__ __launch_bounds__(256) void k4(const float* __restrict__ x,
                                          const float* __restrict__ agg,
                                          float* __restrict__ out) {
    extern __shared__ __align__(16) char sm[];
    const int n0 = blockIdx.x * 128, c0 = blockIdx.y * 64;
    float acc[4][2][4] = {};
    gemm_pipe(g_fiT + (size_t)n0 * HS, HS, g_Tt + (size_t)c0 * HS, HS, HS, acc, sm);

    const int tid = threadIdx.x, lane = tid & 31, wid = tid >> 5;
    const int mBase = (wid >> 2) * 64, nBase = (wid & 3) * 16;
    const int r = lane >> 2, cc = (lane & 3) * 2;

    float* smf = (float*)sm;
#pragma unroll
    for (int mf = 0; mf < 4; mf++)
#pragma unroll
        for (int e = 0; e < 2; e++) {
            const int nl = mBase + mf * 16 + r + e * 8;
#pragma unroll
            for (int nf = 0; nf < 2; nf++) {
                const int cl = nBase + nf * 8 + cc;
                smf[(cl + 0) * EPS + nl] = acc[mf][nf][e * 2];
                smf[(cl + 1) * EPS + nl] = acc[mf][nf][e * 2 + 1];
            }
        }
    __syncthreads();

    const float scale = agg[0] * (1.0f / (float)NN);
#pragma unroll
    for (int t = tid; t < 2048; t += 256) {
        const int row = t >> 5, col = (t & 31) * 4;
        float4 v = *(float4*)(smf + row * EPS + col);
        const size_t gi = (size_t)(c0 + row) * NN + n0 + col;
        float4 xv = *(const float4*)(x + gi);
        v.x = xv.x + scale * v.x;  v.y = xv.y + scale * v.y;
        v.z = xv.z + scale * v.z;  v.w = xv.w + scale * v.w;
        *(float4*)(out + gi) = v;
    }
}

// ======================= launch =======================
extern "C" void kernel_launch(void* const* d_in, const int* in_sizes, int n_in,
                              void* d_out, int out_size) {
    const float* features = (const float*)d_in[0];
    const float* Wi       = (const float*)d_in[1];
    const float* bi       = (const float*)d_in[2];
    const float* Wj       = (const float*)d_in[3];
    const float* bj       = (const float*)d_in[4];
    const float* agg      = (const float*)d_in[5];
    float* out = (float*)d_out;

    cudaFuncSetAttribute(k1, cudaFuncAttributeMaxDynamicSharedMemorySize, K_SMEM);
    cudaFuncSetAttribute(k2, cudaFuncAttributeMaxDynamicSharedMemorySize, K_SMEM);
    cudaFuncSetAttribute(k4, cudaFuncAttributeMaxDynamicSharedMemorySize, SMEM_TOT);

    k0_w<<<512, 256>>>(Wi, Wj);
    k1<<<dim3(162, 2), 256, K_SMEM>>>(features, bi, bj);
    k2<<<dim3(8, SPL), 256, K_SMEM>>>(features);
    kred1<<<dim3(32, RG), 256>>>();
    kred2<<<32, 256>>>();
    k4<<<dim3(81, 8), 256, SMEM_TOT>>>(features, agg, out);
}

// round 17
// speedup vs baseline: 1.4085x; 1.1289x over previous
#include <cuda_runtime.h>
#include <cuda_bf16.h>
#include <cstdint>

#define NN   10368
#define CC   512
#define HS   128
#define SPL  81            // n-chunks for T partials
#define NCHK 128           // n per k2 chunk
#define RG   9             // reduction groups (SPL = RG*RG)

// ---------------- device scratch ----------------
__device__ __nv_bfloat16 g_Wcat[256 * CC];            // [256][512] K-major
__device__ __nv_bfloat16 g_fiT[NN * HS];              // fi^T [n][h]
__device__ __nv_bfloat16 g_fj[HS * NN];               // fj [h][n]
__device__ __nv_bfloat16 g_Tp[SPL * HS * CC];         // bf16 T partials [sp][h][c]
__device__ float         g_Tr[RG * HS * CC];          // stage-1 fp32 partials
__device__ __nv_bfloat16 g_Tt[CC * HS];               // T^T [c][h]

// ---------------- helpers ----------------
__device__ __forceinline__ uint32_t smem_u32(const void* p) {
    uint32_t a;
    asm("{ .reg .u64 t; cvta.to.shared.u64 t, %1; cvt.u32.u64 %0, t; }" : "=r"(a) : "l"(p));
    return a;
}
__device__ __forceinline__ void ldsm4(uint32_t addr, uint32_t& r0, uint32_t& r1,
                                      uint32_t& r2, uint32_t& r3) {
    asm volatile("ldmatrix.sync.aligned.m8n8.x4.shared.b16 {%0,%1,%2,%3}, [%4];"
                 : "=r"(r0), "=r"(r1), "=r"(r2), "=r"(r3) : "r"(addr));
}
__device__ __forceinline__ void ldsm4t(uint32_t addr, uint32_t& r0, uint32_t& r1,
                                       uint32_t& r2, uint32_t& r3) {
    asm volatile("ldmatrix.sync.aligned.m8n8.x4.trans.shared.b16 {%0,%1,%2,%3}, [%4];"
                 : "=r"(r0), "=r"(r1), "=r"(r2), "=r"(r3) : "r"(addr));
}
__device__ __forceinline__ void mma_bf16(float* c, uint32_t a0, uint32_t a1, uint32_t a2,
                                         uint32_t a3, uint32_t b0, uint32_t b1) {
    asm volatile("mma.sync.aligned.m16n8k16.row.col.f32.bf16.bf16.f32 "
                 "{%0,%1,%2,%3}, {%4,%5,%6,%7}, {%8,%9}, {%0,%1,%2,%3};"
                 : "+f"(c[0]), "+f"(c[1]), "+f"(c[2]), "+f"(c[3])
                 : "r"(a0), "r"(a1), "r"(a2), "r"(a3), "r"(b0), "r"(b1));
}
#define CP16(dst, src)  asm volatile("cp.async.cg.shared.global [%0], [%1], 16;" :: "r"(dst), "l"(src))
#define CP_COMMIT()     asm volatile("cp.async.commit_group;" ::: "memory")
#define CP_WAIT0()      asm volatile("cp.async.wait_group 0;" ::: "memory")
#define CP_WAIT1()      asm volatile("cp.async.wait_group 1;" ::: "memory")

#define XBS  72            // bf16 smem row stride
#define FIS  136           // fi staging stride (bf16)

// ---- shared smem layout for k1/k2 (bytes) ----
#define A_OFF   0                      // A bf16 stages x2: [128][72]x2B = 18432 each
#define A_ST    18432
#define XC_OFF  36864                  // converted bf16 x, double buffer [64][72]x2B
#define XC_ST   9216
#define K_SMEM  55296

// x fp32 -> regs -> bf16 smem: each thread owns 4 float4 (c = idx>>4, q = (idx&15)*4)
struct XReg { float4 v[4]; };

__device__ __forceinline__ void ldX(XReg& xr, const float* __restrict__ xbase,
                                    int tid) {
#pragma unroll
    for (int i = 0; i < 4; i++) {
        const int idx = tid + i * 256;
        const int c = idx >> 4, q = (idx & 15) * 4;
        xr.v[i] = *(const float4*)(xbase + (size_t)c * NN + q);
    }
}
__device__ __forceinline__ void stX(const XReg& xr, char* sm, uint32_t xcoff, int tid) {
    __nv_bfloat16* xc = (__nv_bfloat16*)(sm + xcoff);
#pragma unroll
    for (int i = 0; i < 4; i++) {
        const int idx = tid + i * 256;
        const int c = idx >> 4, q = (idx & 15) * 4;
        __nv_bfloat162 h0 = __floats2bfloat162_rn(xr.v[i].x, xr.v[i].y);
        __nv_bfloat162 h1 = __floats2bfloat162_rn(xr.v[i].z, xr.v[i].w);
        uint2 o; o.x = *(uint32_t*)&h0; o.y = *(uint32_t*)&h1;
        *(uint2*)(xc + (size_t)c * XBS + q) = o;
    }
}

// ======================= k1: f = Wcat @ x, reg-convert =======================
// grid (162, 2): n0 = bx*64, m0 = by*128.  K = 512 (8 chunks of 64).
__global__ __launch_bounds__(256) void k1(const float* __restrict__ x,
                                          const float* __restrict__ bi,
                                          const float* __restrict__ bj) {
    extern __shared__ __align__(16) char sm[];
    const uint32_t sb = smem_u32(sm);
    const int tid = threadIdx.x, lane = tid & 31, wid = tid >> 5;
    const int n0 = blockIdx.x * 64, m0 = blockIdx.y * 128;

    const int mBase = (wid >> 1) * 32, nB1 = (wid & 1) * 32;
    float acc[2][4][4] = {};

    auto cpA = [&](int s) {
        const uint32_t st = sb + A_OFF + (s & 1) * A_ST;
#pragma unroll
        for (int i = tid; i < 1024; i += 256) {
            const int row = i >> 3, q = (i & 7) * 8;
            CP16(st + (uint32_t)(row * XBS + q) * 2,
                 g_Wcat + (size_t)(m0 + row) * CC + s * 64 + q);
        }
    };

    XReg xr;
    cpA(0); CP_COMMIT();
    ldX(xr, x + (size_t)0 * NN + n0, tid);
    for (int s = 0; s < 8; s++) {
        if (s < 7) { cpA(s + 1); CP_COMMIT(); }
        stX(xr, sm, XC_OFF + (s & 1) * XC_ST, tid);
        if (s < 7) ldX(xr, x + (size_t)(s + 1) * 64 * NN + n0, tid);   // fly during mma
        if (s < 7) { CP_WAIT1(); } else { CP_WAIT0(); }
        __syncthreads();
        const uint32_t stA = sb + A_OFF + (s & 1) * A_ST;
        const uint32_t stX_ = sb + XC_OFF + (s & 1) * XC_ST;
#pragma unroll
        for (int kk = 0; kk < 4; kk++) {
            uint32_t af[2][4], bf[2][4];
#pragma unroll
            for (int mf = 0; mf < 2; mf++)
                ldsm4(stA + (uint32_t)((mBase + mf * 16 + (lane & 15)) * XBS
                                       + kk * 16 + (lane >> 4) * 8) * 2,
                      af[mf][0], af[mf][1], af[mf][2], af[mf][3]);
#pragma unroll
            for (int nt = 0; nt < 2; nt++) {
                const int crow = kk * 16 + (lane & 7) + (((lane >> 3) & 1) << 3);
                const int ncol = nB1 + nt * 16 + ((lane >> 4) << 3);
                ldsm4t(stX_ + (uint32_t)(crow * XBS + ncol) * 2,
                       bf[nt][0], bf[nt][1], bf[nt][2], bf[nt][3]);
            }
#pragma unroll
            for (int mf = 0; mf < 2; mf++)
#pragma unroll
                for (int nq = 0; nq < 2; nq++) {
                    mma_bf16(acc[mf][nq * 2],     af[mf][0], af[mf][1], af[mf][2], af[mf][3],
                             bf[nq][0], bf[nq][1]);
                    mma_bf16(acc[mf][nq * 2 + 1], af[mf][0], af[mf][1], af[mf][2], af[mf][3],
                             bf[nq][2], bf[nq][3]);
                }
        }
        __syncthreads();   // protect A[s&1] / XC[s&1] before next-iter overwrites
    }

    const int r = lane >> 2, cc2 = (lane & 3) * 2;
    if (m0 == 0) {
        __nv_bfloat16* fiS = (__nv_bfloat16*)(sm + A_OFF);
#pragma unroll
        for (int mf = 0; mf < 2; mf++)
#pragma unroll
            for (int e = 0; e < 2; e++) {
                const int m = mBase + mf * 16 + r + e * 8;
                const float bias = bi[m];
#pragma unroll
                for (int nf = 0; nf < 4; nf++) {
                    const int nl = nB1 + nf * 8 + cc2;
                    fiS[(nl + 0) * FIS + m] = __float2bfloat16(acc[mf][nf][e * 2] + bias);
                    fiS[(nl + 1) * FIS + m] = __float2bfloat16(acc[mf][nf][e * 2 + 1] + bias);
                }
            }
        __syncthreads();
#pragma unroll
        for (int i = tid; i < 1024; i += 256) {
            const int row = i >> 4, q = (i & 15) * 8;
            *(uint4*)(g_fiT + (size_t)(n0 + row) * HS + q) = *(uint4*)(fiS + row * FIS + q);
        }
    } else {
        __nv_bfloat16* fjS = (__nv_bfloat16*)(sm + A_OFF);
#pragma unroll
        for (int mf = 0; mf < 2; mf++)
#pragma unroll
            for (int e = 0; e < 2; e++) {
                const int hh = mBase + mf * 16 + r + e * 8;
                const float bias = bj[hh];
#pragma unroll
                for (int nf = 0; nf < 4; nf++) {
                    const int nl = nB1 + nf * 8 + cc2;
                    *(__nv_bfloat162*)(fjS + hh * XBS + nl) =
                        __floats2bfloat162_rn(acc[mf][nf][e * 2] + bias,
                                              acc[mf][nf][e * 2 + 1] + bias);
                }
            }
        __syncthreads();
#pragma unroll
        for (int i = tid; i < 1024; i += 256) {
            const int row = i >> 3, q = (i & 7) * 8;
            *(uint4*)(g_fj + (size_t)row * NN + n0 + q) = *(uint4*)(fjS + row * XBS + q);
        }
    }
}

// ======================= k2: Tp[sp] = fj @ x^T, reg-convert =======================
// grid (8, 81): c0 = bx*64, chunk sp = by (128 n).  K = 128 (2 chunks of 64).
__global__ __launch_bounds__(256) void k2(const float* __restrict__ x) {
    extern __shared__ __align__(16) char sm[];
    const uint32_t sb = smem_u32(sm);
    const int tid = threadIdx.x, lane = tid & 31, wid = tid >> 5;
    const int c0 = blockIdx.x * 64, nb = blockIdx.y * NCHK;

    const int mBase = (wid >> 1) * 32, cB = (wid & 1) * 32;
    float acc[2][4][4] = {};

    auto cpA = [&](int s) {
        const uint32_t st = sb + A_OFF + (s & 1) * A_ST;
#pragma unroll
        for (int i = tid; i < 1024; i += 256) {
            const int row = i >> 3, q = (i & 7) * 8;
            CP16(st + (uint32_t)(row * XBS + q) * 2,
                 g_fj + (size_t)row * NN + nb + s * 64 + q);
        }
    };

    XReg xr;
    cpA(0); CP_COMMIT();
    ldX(xr, x + (size_t)c0 * NN + nb, tid);
    for (int s = 0; s < 2; s++) {
        if (s < 1) { cpA(1); CP_COMMIT(); }
        stX(xr, sm, XC_OFF + (s & 1) * XC_ST, tid);
        if (s < 1) ldX(xr, x + (size_t)c0 * NN + nb + 64, tid);
        if (s < 1) { CP_WAIT1(); } else { CP_WAIT0(); }
        __syncthreads();
        const uint32_t stA = sb + A_OFF + (s & 1) * A_ST;
        const uint32_t stX_ = sb + XC_OFF + (s & 1) * XC_ST;
        const int b_r = ((lane >> 4) << 3) + (lane & 7), b_k = ((lane >> 3) & 1) * 8;
#pragma unroll
        for (int kk = 0; kk < 4; kk++) {
            uint32_t af[2][4], bf[2][4];
#pragma unroll
            for (int mf = 0; mf < 2; mf++)
                ldsm4(stA + (uint32_t)((mBase + mf * 16 + (lane & 15)) * XBS
                                       + kk * 16 + (lane >> 4) * 8) * 2,
                      af[mf][0], af[mf][1], af[mf][2], af[mf][3]);
#pragma unroll
            for (int nq = 0; nq < 2; nq++)
                ldsm4(stX_ + (uint32_t)((cB + nq * 16 + b_r) * XBS
                                        + kk * 16 + b_k) * 2,
                      bf[nq][0], bf[nq][1], bf[nq][2], bf[nq][3]);
#pragma unroll
            for (int mf = 0; mf < 2; mf++)
#pragma unroll
                for (int nq = 0; nq < 2; nq++) {
                    mma_bf16(acc[mf][nq * 2],     af[mf][0], af[mf][1], af[mf][2], af[mf][3],
                             bf[nq][0], bf[nq][1]);
                    mma_bf16(acc[mf][nq * 2 + 1], af[mf][0], af[mf][1], af[mf][2], af[mf][3],
                             bf[nq][2], bf[nq][3]);
                }
        }
        __syncthreads();
    }

    __nv_bfloat16* tS = (__nv_bfloat16*)(sm + A_OFF);
    const int r = lane >> 2, cc2 = (lane & 3) * 2;
#pragma unroll
    for (int mf = 0; mf < 2; mf++)
#pragma unroll
        for (int e = 0; e < 2; e++) {
            const int hh = mBase + mf * 16 + r + e * 8;
#pragma unroll
            for (int nf = 0; nf < 4; nf++) {
                const int cl = cB + nf * 8 + cc2;
                *(__nv_bfloat162*)(tS + hh * XBS + cl) =
                    __floats2bfloat162_rn(acc[mf][nf][e * 2], acc[mf][nf][e * 2 + 1]);
            }
        }
    __syncthreads();
    __nv_bfloat16* dst = g_Tp + (size_t)blockIdx.y * HS * CC + c0;
#pragma unroll
    for (int i = tid; i < 1024; i += 256) {
        const int row = i >> 3, q = (i & 7) * 8;
        *(uint4*)(dst + (size_t)row * CC + q) = *(uint4*)(tS + row * XBS + q);
    }
}

// ======================= k0: weights -> bf16 concat =======================
__global__ void k0_w(const float* __restrict__ Wi, const float* __restrict__ Wj) {
    int i = blockIdx.x * 256 + threadIdx.x;
    if (i < 256 * CC)
        g_Wcat[i] = __float2bfloat16(i < HS * CC ? Wi[i] : Wj[i - HS * CC]);
}

// ======================= kred1: stage-1 tree reduce, 8B/thread =======================
// grid (64, 9), block 256
__global__ void kred1() {
    const int g = blockIdx.y;
    const int idx = blockIdx.x * 256 + threadIdx.x;       // 16384 per group
    const int i4 = idx * 4;                               // 4 bf16 = 8 B
    float s[4] = {};
#pragma unroll
    for (int pp = 0; pp < RG; pp++) {
        const int p = g * RG + pp;
        uint2 v = *(const uint2*)(g_Tp + (size_t)p * HS * CC + i4);
        const __nv_bfloat162* b = (const __nv_bfloat162*)&v;
#pragma unroll
        for (int j = 0; j < 2; j++) {
            float2 f = __bfloat1622float2(b[j]);
            s[2 * j] += f.x; s[2 * j + 1] += f.y;
        }
    }
    *(float4*)(g_Tr + (size_t)g * HS * CC + i4) = make_float4(s[0], s[1], s[2], s[3]);
}

// ======================= kred2: stage-2 reduce + transpose to Tt =======================
// grid 64, block 256
__global__ void kred2() {
    const int idx = blockIdx.x * 256 + threadIdx.x;       // 16384 threads
    const int i4 = idx * 4;
    const int h = i4 >> 9, c0 = i4 & 511;
    float s[4] = {};
#pragma unroll
    for (int g = 0; g < RG; g++) {
        float4 v = *(const float4*)(g_Tr + (size_t)g * HS * CC + i4);
        s[0] += v.x; s[1] += v.y; s[2] += v.z; s[3] += v.w;
    }
#pragma unroll
    for (int j = 0; j < 4; j++)
        g_Tt[(size_t)(c0 + j) * HS + h] = __float2bfloat16(s[j]);
}

// ======================= k4: out = x + scale * (fiT @ Tt^T)^T =======================
#define SM_STRIDE 72
#define STAGE_A   (128 * SM_STRIDE * 2)
#define STAGE_B   (64 * SM_STRIDE * 2)
#define STAGE_SZ  (STAGE_A + STAGE_B)
#define SMEM_TOT  (2 * STAGE_SZ)
#define EPS 132

__device__ __forceinline__ void gemm_pipe(const __nv_bfloat16* __restrict__ Ag, size_t lda,
                                          const __nv_bfloat16* __restrict__ Bg, size_t ldb,
                                          int K, float acc[4][2][4], char* sm) {
    const int tid = threadIdx.x, lane = tid & 31, wid = tid >> 5;
    const int mBase = (wid >> 2) * 64, nBase = (wid & 3) * 16;
    const uint32_t sbase = smem_u32(sm);

    const int a_r = lane & 15, a_k = (lane >> 4) * 8;
    const int b_r = ((lane >> 4) << 3) + (lane & 7), b_k = ((lane >> 3) & 1) * 8;
    const uint32_t aOff = (uint32_t)((mBase + a_r) * SM_STRIDE + a_k) * 2;
    const uint32_t bOff = (uint32_t)(STAGE_A + ((nBase + b_r) * SM_STRIDE + b_k) * 2);

    const int nstages = K / 64;
    auto load_stage = [&](int s, int k0) {
        const uint32_t st = sbase + s * STAGE_SZ;
#pragma unroll
        for (int i = tid; i < 1536; i += 256) {
            const int which = (i >= 1024);
            const int idx = which ? (i - 1024) : i;
            const int row = idx >> 3, q = (idx & 7) * 8;
            const uint32_t dst = st + which * STAGE_A + (uint32_t)(row * SM_STRIDE + q) * 2;
            const __nv_bfloat16* src = which ? (Bg + (size_t)row * ldb + k0 + q)
                                             : (Ag + (size_t)row * lda + k0 + q);
            CP16(dst, src);
        }
    };

    load_stage(0, 0);
    CP_COMMIT();
    int cur = 0;
    for (int s = 1; s <= nstages; s++) {
        CP_WAIT0();
        __syncthreads();
        if (s < nstages) { load_stage(cur ^ 1, s * 64); CP_COMMIT(); }
        const uint32_t stA = sbase + cur * STAGE_SZ + aOff;
        const uint32_t stB = sbase + cur * STAGE_SZ + bOff;
#pragma unroll
        for (int kk = 0; kk < 4; kk++) {
            uint32_t af[4][4], bf[4];
#pragma unroll
            for (int mf = 0; mf < 4; mf++)
                ldsm4(stA + (uint32_t)(mf * 16 * SM_STRIDE + kk * 16) * 2,
                      af[mf][0], af[mf][1], af[mf][2], af[mf][3]);
            ldsm4(stB + (uint32_t)(kk * 16) * 2, bf[0], bf[1], bf[2], bf[3]);
#pragma unroll
            for (int mf = 0; mf < 4; mf++) {
                mma_bf16(acc[mf][0], af[mf][0], af[mf][1], af[mf][2], af[mf][3], bf[0], bf[1]);
                mma_bf16(acc[mf][1], af[mf][0], af[mf][1], af[mf][2], af[mf][3], bf[2], bf[3]);
            }
        }
        __syncthreads();
        cur ^= 1;
    }
}

__global__ __launch_bounds__(256) void k4(const float* __restrict__ x,
                                          const float* __restrict__ agg,
                                          float* __restrict__ out) {
    extern __shared__ __align__(16) char sm[];
    const int n0 = blockIdx.x * 128, c0 = blockIdx.y * 64;
    float acc[4][2][4] = {};
    gemm_pipe(g_fiT + (size_t)n0 * HS, HS, g_Tt + (size_t)c0 * HS, HS, HS, acc, sm);

    const int tid = threadIdx.x, lane = tid & 31, wid = tid >> 5;
    const int mBase = (wid >> 2) * 64, nBase = (wid & 3) * 16;
    const int r = lane >> 2, cc = (lane & 3) * 2;

    float* smf = (float*)sm;
#pragma unroll
    for (int mf = 0; mf < 4; mf++)
#pragma unroll
        for (int e = 0; e < 2; e++) {
            const int nl = mBase + mf * 16 + r + e * 8;
#pragma unroll
            for (int nf = 0; nf < 2; nf++) {
                const int cl = nBase + nf * 8 + cc;
                smf[(cl + 0) * EPS + nl] = acc[mf][nf][e * 2];
                smf[(cl + 1) * EPS + nl] = acc[mf][nf][e * 2 + 1];
            }
        }
    __syncthreads();

    const float scale = agg[0] * (1.0f / (float)NN);
#pragma unroll
    for (int t = tid; t < 2048; t += 256) {
        const int row = t >> 5, col = (t & 31) * 4;
        float4 v = *(float4*)(smf + row * EPS + col);
        const size_t gi = (size_t)(c0 + row) * NN + n0 + col;
        float4 xv = *(const float4*)(x + gi);
        v.x = xv.x + scale * v.x;  v.y = xv.y + scale * v.y;
        v.z = xv.z + scale * v.z;  v.w = xv.w + scale * v.w;
        *(float4*)(out + gi) = v;
    }
}

// ======================= launch =======================
extern "C" void kernel_launch(void* const* d_in, const int* in_sizes, int n_in,
                              void* d_out, int out_size) {
    const float* features = (const float*)d_in[0];
    const float* Wi       = (const float*)d_in[1];
    const float* bi       = (const float*)d_in[2];
    const float* Wj       = (const float*)d_in[3];
    const float* bj       = (const float*)d_in[4];
    const float* agg      = (const float*)d_in[5];
    float* out = (float*)d_out;

    cudaFuncSetAttribute(k1, cudaFuncAttributeMaxDynamicSharedMemorySize, K_SMEM);
    cudaFuncSetAttribute(k2, cudaFuncAttributeMaxDynamicSharedMemorySize, K_SMEM);
    cudaFuncSetAttribute(k4, cudaFuncAttributeMaxDynamicSharedMemorySize, SMEM_TOT);

    k0_w<<<512, 256>>>(Wi, Wj);
    k1<<<dim3(162, 2), 256, K_SMEM>>>(features, bi, bj);
    k2<<<dim3(8, SPL), 256, K_SMEM>>>(features);
    kred1<<<dim3(64, RG), 256>>>();
    kred2<<<64, 256>>>();
    k4<<<dim3(81, 8), 256, SMEM_TOT>>>(features, agg, out);
}